// round 8
// baseline (speedup 1.0000x reference)
#include <cuda_runtime.h>
#include <math.h>
#include <stdint.h>

#define Bc 8
#define Nn 1024
#define Dm 1024
#define Hh 16
#define HD 64
#define Tt_ 8192
#define NE 4
#define MH 2048

// ---------------- scratch (static device allocations only) ----------------
__device__ __align__(16) float g_scratch[(size_t)14 * 8 * 1024 * 1024];
__device__ int g_iscratch[64 + NE * Tt_];

// ---------------- transpose: in [B][R=1024][C=1024] -> out [B][C][R] --------
__global__ void k_transpose(const float* __restrict__ in, float* __restrict__ out) {
    __shared__ float tile[32][33];
    int b = blockIdx.z;
    int c0 = blockIdx.x * 32, r0 = blockIdx.y * 32;
    const float* ip = in + (size_t)b * Nn * Dm;
    float* op = out + (size_t)b * Nn * Dm;
    int tx = threadIdx.x, ty = threadIdx.y;
#pragma unroll
    for (int i = 0; i < 32; i += 8)
        tile[ty + i][tx] = ip[(size_t)(r0 + ty + i) * Dm + c0 + tx];
    __syncthreads();
#pragma unroll
    for (int i = 0; i < 32; i += 8)
        op[(size_t)(c0 + ty + i) * Nn + r0 + tx] = tile[tx][ty + i];
}

// ---------------- decomposition: 3 depthwise reflect convs, softmax-mixed ---
__global__ void k_decomp(const float* __restrict__ xt, const float* __restrict__ dw7,
                         const float* __restrict__ dw25, const float* __restrict__ dw49,
                         const float* __restrict__ alpha, float* __restrict__ trt) {
    int d = blockIdx.x, b = blockIdx.y;
    __shared__ float row[Nn];
    __shared__ float kw[96];
    int tid = threadIdx.x;
    const float* xr = xt + ((size_t)b * Dm + d) * Nn;
    for (int i = tid; i < Nn; i += blockDim.x) row[i] = xr[i];
    if (tid < 7) kw[tid] = dw7[d * 7 + tid];
    if (tid < 25) kw[7 + tid] = dw25[d * 25 + tid];
    if (tid < 49) kw[32 + tid] = dw49[d * 49 + tid];
    __syncthreads();
    float a0 = alpha[0], a1 = alpha[1], a2 = alpha[2];
    float mx = fmaxf(a0, fmaxf(a1, a2));
    float e0 = expf(a0 - mx), e1 = expf(a1 - mx), e2 = expf(a2 - mx);
    float inv = 1.f / (e0 + e1 + e2);
    float w0 = e0 * inv, w1 = e1 * inv, w2 = e2 * inv;
    float* out = trt + ((size_t)b * Dm + d) * Nn;
    for (int n = tid; n < Nn; n += blockDim.x) {
        float acc = 0.f;
#pragma unroll
        for (int j = 0; j < 7; j++) {
            int t = n - 3 + j; t = t < 0 ? -t : (t >= Nn ? 2 * (Nn - 1) - t : t);
            acc += w0 * kw[j] * row[t];
        }
#pragma unroll
        for (int j = 0; j < 25; j++) {
            int t = n - 12 + j; t = t < 0 ? -t : (t >= Nn ? 2 * (Nn - 1) - t : t);
            acc += w1 * kw[7 + j] * row[t];
        }
#pragma unroll
        for (int j = 0; j < 49; j++) {
            int t = n - 24 + j; t = t < 0 ? -t : (t >= Nn ? 2 * (Nn - 1) - t : t);
            acc += w2 * kw[32 + j] * row[t];
        }
        out[n] = acc;
    }
}

// ---------------- S[b,n,d] = x[b,n,d] - Trt[b,d,n] (tiled transpose-sub) ----
__global__ void k_makeS(const float* __restrict__ x, const float* __restrict__ trt,
                        float* __restrict__ S) {
    __shared__ float tile[32][33];
    int b = blockIdx.z;
    int d0 = blockIdx.x * 32, n0 = blockIdx.y * 32;
    int tx = threadIdx.x, ty = threadIdx.y;
#pragma unroll
    for (int i = 0; i < 32; i += 8)
        tile[ty + i][tx] = trt[(size_t)b * Dm * Nn + (size_t)(d0 + ty + i) * Nn + n0 + tx];
    __syncthreads();
#pragma unroll
    for (int i = 0; i < 32; i += 8) {
        size_t idx = (size_t)b * Nn * Dm + (size_t)(n0 + ty + i) * Dm + d0 + tx;
        S[idx] = x[idx] - tile[tx][ty + i];
    }
}

// ---------------- out[b,n,d] = xs[b,n,d] + Tt[b,d,n] ------------------------
__global__ void k_final(const float* __restrict__ xs, const float* __restrict__ tt,
                        float* __restrict__ out) {
    __shared__ float tile[32][33];
    int b = blockIdx.z;
    int d0 = blockIdx.x * 32, n0 = blockIdx.y * 32;
    int tx = threadIdx.x, ty = threadIdx.y;
#pragma unroll
    for (int i = 0; i < 32; i += 8)
        tile[ty + i][tx] = tt[(size_t)b * Dm * Nn + (size_t)(d0 + ty + i) * Nn + n0 + tx];
    __syncthreads();
#pragma unroll
    for (int i = 0; i < 32; i += 8) {
        size_t idx = (size_t)b * Nn * Dm + (size_t)(n0 + ty + i) * Dm + d0 + tx;
        out[idx] = xs[idx] + tile[tx][ty + i];
    }
}

// ---------------- layernorm over last dim (1024) ---------------------------
__global__ void k_ln(const float* __restrict__ x, const float* __restrict__ g,
                     const float* __restrict__ bta, float* __restrict__ out) {
    int row = blockIdx.x;
    int tid = threadIdx.x;
    const float* xr = x + (size_t)row * Dm;
    __shared__ float red[256];
    float s = 0.f;
    for (int i = tid; i < Dm; i += 256) s += xr[i];
    red[tid] = s; __syncthreads();
    for (int st = 128; st > 0; st >>= 1) { if (tid < st) red[tid] += red[tid + st]; __syncthreads(); }
    float mean = red[0] / Dm;
    __syncthreads();
    float v = 0.f;
    for (int i = tid; i < Dm; i += 256) { float dd = xr[i] - mean; v += dd * dd; }
    red[tid] = v; __syncthreads();
    for (int st = 128; st > 0; st >>= 1) { if (tid < st) red[tid] += red[tid + st]; __syncthreads(); }
    float inv = rsqrtf(red[0] / Dm + 1e-5f);
    for (int i = tid; i < Dm; i += 256)
        out[(size_t)row * Dm + i] = (xr[i] - mean) * inv * g[i] + bta[i];
}

// ---------------- TF32 tensor-core NT GEMM: C = A[M,K]*Bm[N,K]^T + bias -----
// 128x128x16 block, 4 warps, 64x64 warp tiles, permuted-k smem for float2
// fragment loads. Contract identical to previous k_sgemm.
__device__ __forceinline__ float4 cvt4_tf32(float4 v) {
    uint32_t a, b, c, d;
    asm("cvt.rna.tf32.f32 %0,%1;" : "=r"(a) : "f"(v.x));
    asm("cvt.rna.tf32.f32 %0,%1;" : "=r"(b) : "f"(v.y));
    asm("cvt.rna.tf32.f32 %0,%1;" : "=r"(c) : "f"(v.z));
    asm("cvt.rna.tf32.f32 %0,%1;" : "=r"(d) : "f"(v.w));
    float4 r;
    r.x = __uint_as_float(a); r.y = __uint_as_float(b);
    r.z = __uint_as_float(c); r.w = __uint_as_float(d);
    return r;
}

__device__ __forceinline__ void mma_tf32(float c[4], const uint32_t a[4], const uint32_t b[2]) {
    asm volatile(
        "mma.sync.aligned.m16n8k8.row.col.f32.tf32.tf32.f32 "
        "{%0,%1,%2,%3},{%4,%5,%6,%7},{%8,%9},{%0,%1,%2,%3};"
        : "+f"(c[0]), "+f"(c[1]), "+f"(c[2]), "+f"(c[3])
        : "r"(a[0]), "r"(a[1]), "r"(a[2]), "r"(a[3]), "r"(b[0]), "r"(b[1]));
}

// store 16 k-consecutive floats (4 float4) into permuted smem row:
// within each 8-group, slot = 2*(k&3) + (k>>2)  -> pair (k, k+4) adjacent
__device__ __forceinline__ void store_perm_row(float* row, float4 f0, float4 f1,
                                               float4 f2, float4 f3) {
    f0 = cvt4_tf32(f0); f1 = cvt4_tf32(f1); f2 = cvt4_tf32(f2); f3 = cvt4_tf32(f3);
    *(float4*)(row + 0)  = make_float4(f0.x, f1.x, f0.y, f1.y);
    *(float4*)(row + 4)  = make_float4(f0.z, f1.z, f0.w, f1.w);
    *(float4*)(row + 8)  = make_float4(f2.x, f3.x, f2.y, f3.y);
    *(float4*)(row + 12) = make_float4(f2.z, f3.z, f2.w, f3.w);
}

#define SMS 20  // smem row stride (floats)

__global__ void __launch_bounds__(128) k_sgemm(
    const float* __restrict__ A, const float* __restrict__ Bm,
    const float* __restrict__ bias, const float* __restrict__ res,
    float* __restrict__ C, int M, const int* __restrict__ Mdev,
    int Npar, int K, const int* __restrict__ gidx,
    const float* __restrict__ gscale, int gelu_flag) {
    if (Mdev) M = *Mdev;
    int bm = blockIdx.y * 128, bn = blockIdx.x * 128;
    if (bm >= M) return;
    __shared__ __align__(16) float As[2][128][SMS];
    __shared__ __align__(16) float Bs[2][128][SMS];
    int tid = threadIdx.x;
    int warp = tid >> 5, lane = tid & 31;
    int wm = (warp & 1) * 64, wn = (warp >> 1) * 64;
    int qd = lane >> 2, rr = lane & 3;

    float c[4][8][4];
#pragma unroll
    for (int i = 0; i < 4; i++)
#pragma unroll
        for (int j = 0; j < 8; j++)
#pragma unroll
            for (int l = 0; l < 4; l++) c[i][j][l] = 0.f;

    int lrow = tid;  // one 16-wide k-row per thread for both A and B
    int am = bm + lrow;
    bool av = am < M;
    int asrc = 0;
    if (av) asrc = (gidx && !gscale) ? gidx[am] : am;
    const float* Ap = A + (size_t)asrc * K;
    const float* Bp = Bm + (size_t)(bn + lrow) * K;

    const float4 z4 = make_float4(0.f, 0.f, 0.f, 0.f);
    float4 fa0, fa1, fa2, fa3, fb0, fb1, fb2, fb3;

    // prologue: tile 0
    fa0 = av ? *(const float4*)(Ap + 0) : z4;
    fa1 = av ? *(const float4*)(Ap + 4) : z4;
    fa2 = av ? *(const float4*)(Ap + 8) : z4;
    fa3 = av ? *(const float4*)(Ap + 12) : z4;
    fb0 = *(const float4*)(Bp + 0);
    fb1 = *(const float4*)(Bp + 4);
    fb2 = *(const float4*)(Bp + 8);
    fb3 = *(const float4*)(Bp + 12);
    store_perm_row(&As[0][lrow][0], fa0, fa1, fa2, fa3);
    store_perm_row(&Bs[0][lrow][0], fb0, fb1, fb2, fb3);
    __syncthreads();

    int ntiles = K >> 4;
    for (int kt = 0; kt < ntiles; kt++) {
        int buf = kt & 1;
        if (kt + 1 < ntiles) {
            const float* ap = Ap + (size_t)(kt + 1) * 16;
            const float* bp = Bp + (size_t)(kt + 1) * 16;
            fa0 = av ? *(const float4*)(ap + 0) : z4;
            fa1 = av ? *(const float4*)(ap + 4) : z4;
            fa2 = av ? *(const float4*)(ap + 8) : z4;
            fa3 = av ? *(const float4*)(ap + 12) : z4;
            fb0 = *(const float4*)(bp + 0);
            fb1 = *(const float4*)(bp + 4);
            fb2 = *(const float4*)(bp + 8);
            fb3 = *(const float4*)(bp + 12);
        }
#pragma unroll
        for (int ks = 0; ks < 2; ks++) {
            int kc = ks * 8 + 2 * rr;
            uint32_t af[4][4];
#pragma unroll
            for (int mi = 0; mi < 4; mi++) {
                int rb = wm + mi * 16;
                float2 f0 = *(const float2*)&As[buf][rb + qd][kc];
                float2 f1 = *(const float2*)&As[buf][rb + qd + 8][kc];
                af[mi][0] = __float_as_uint(f0.x);
                af[mi][1] = __float_as_uint(f1.x);
                af[mi][2] = __float_as_uint(f0.y);
                af[mi][3] = __float_as_uint(f1.y);
            }
            uint32_t bf[8][2];
#pragma unroll
            for (int ni = 0; ni < 8; ni++) {
                float2 fb = *(const float2*)&Bs[buf][wn + ni * 8 + qd][kc];
                bf[ni][0] = __float_as_uint(fb.x);
                bf[ni][1] = __float_as_uint(fb.y);
            }
#pragma unroll
            for (int mi = 0; mi < 4; mi++)
#pragma unroll
                for (int ni = 0; ni < 8; ni++)
                    mma_tf32(c[mi][ni], af[mi], bf[ni]);
        }
        if (kt + 1 < ntiles) {
            int nb = (kt + 1) & 1;
            store_perm_row(&As[nb][lrow][0], fa0, fa1, fa2, fa3);
            store_perm_row(&Bs[nb][lrow][0], fb0, fb1, fb2, fb3);
        }
        __syncthreads();
    }

    // epilogue
#pragma unroll
    for (int mi = 0; mi < 4; mi++) {
#pragma unroll
        for (int hf = 0; hf < 2; hf++) {
            int m = bm + wm + mi * 16 + qd + hf * 8;
            if (m >= M) continue;
            int cr = gscale ? gidx[m] : m;
            float scv = gscale ? gscale[m] : 1.f;
            float* Crow = C + (size_t)cr * Npar;
            const float* Rrow = res ? res + (size_t)m * Npar : nullptr;
#pragma unroll
            for (int ni = 0; ni < 8; ni++) {
                int n = bn + wn + ni * 8 + 2 * rr;
                float v0 = c[mi][ni][hf * 2 + 0] + (bias ? bias[n] : 0.f);
                float v1 = c[mi][ni][hf * 2 + 1] + (bias ? bias[n + 1] : 0.f);
                if (gelu_flag) {
                    v0 = 0.5f * v0 * (1.f + erff(v0 * 0.70710678118654752f));
                    v1 = 0.5f * v1 * (1.f + erff(v1 * 0.70710678118654752f));
                }
                if (gscale) {
                    Crow[n] += v0 * scv;
                    Crow[n + 1] += v1 * scv;
                } else {
                    Crow[n] = v0 + (Rrow ? Rrow[n] : 0.f);
                    Crow[n + 1] = v1 + (Rrow ? Rrow[n + 1] : 0.f);
                }
            }
        }
    }
}

// ---------------- flash-style ALiBi attention (2 lanes per query) ----------
__global__ void __launch_bounds__(128) k_attn(const float* __restrict__ q,
                                              const float* __restrict__ k,
                                              const float* __restrict__ v,
                                              float* __restrict__ y) {
    int qt = blockIdx.x, h = blockIdx.y, b = blockIdx.z;
    int t = threadIdx.x;
    int qi = qt * 64 + (t >> 1);
    int half = (t & 1) * 32;
    __shared__ float Ks[64][64];
    __shared__ float Vs[64][64];
    float qr[32];
    const float* qp = q + ((size_t)(b * Nn + qi) * Dm + h * HD + half);
#pragma unroll
    for (int c = 0; c < 32; c += 4) {
        float4 f = *(const float4*)(qp + c);
        qr[c] = f.x; qr[c + 1] = f.y; qr[c + 2] = f.z; qr[c + 3] = f.w;
    }
    float o[32];
#pragma unroll
    for (int c = 0; c < 32; c++) o[c] = 0.f;
    float m = -1e30f, l = 0.f;
    float slope = exp2f(-0.5f * (float)(h + 1));
    for (int c0 = 0; c0 < Nn; c0 += 64) {
        for (int idx = t; idx < 64 * 64; idx += 128) {
            int row = idx >> 6, col = idx & 63;
            size_t base = ((size_t)(b * Nn + c0 + row) * Dm + h * HD);
            Ks[row][col] = k[base + col];
            Vs[row][col] = v[base + col];
        }
        __syncthreads();
        for (int j = 0; j < 64; j++) {
            float s0 = 0.f, s1 = 0.f, s2 = 0.f, s3 = 0.f;
            const float* kr = &Ks[j][half];
#pragma unroll
            for (int c = 0; c < 32; c += 4) {
                s0 += qr[c] * kr[c];
                s1 += qr[c + 1] * kr[c + 1];
                s2 += qr[c + 2] * kr[c + 2];
                s3 += qr[c + 3] * kr[c + 3];
            }
            float s = s0 + s1 + s2 + s3;
            s += __shfl_xor_sync(0xffffffffu, s, 1);
            s *= 0.125f;
            int dj = (c0 + j) - qi;
            if (dj > 0) s -= slope * (float)dj;
            float mn = fmaxf(m, s);
            float p = expf(s - mn);
            if (mn > m) {
                float corr = expf(m - mn);
                l *= corr;
#pragma unroll
                for (int c = 0; c < 32; c++) o[c] *= corr;
            }
            m = mn;
            l += p;
            const float* vr = &Vs[j][half];
#pragma unroll
            for (int c = 0; c < 32; c++) o[c] += p * vr[c];
        }
        __syncthreads();
    }
    float invl = 1.f / l;
    float* yp = y + ((size_t)(b * Nn + qi) * Dm + h * HD + half);
#pragma unroll
    for (int c = 0; c < 32; c++) yp[c] = o[c] * invl;
}

// ---------------- router: softmax gates, top-2, expert lists, aux sums -----
__global__ void k_router(const float* __restrict__ xf, const float* __restrict__ rw,
                         float* __restrict__ gatesum, int* __restrict__ icnt,
                         int* __restrict__ idxbuf, float* __restrict__ gwbuf) {
    int t = blockIdx.x;
    int tid = threadIdx.x;  // 128
    const float* xr = xf + (size_t)t * Dm;
    float a0 = 0.f, a1 = 0.f, a2 = 0.f, a3 = 0.f;
    for (int i = tid; i < Dm; i += 128) {
        float xv = xr[i];
        a0 += xv * rw[i];
        a1 += xv * rw[Dm + i];
        a2 += xv * rw[2 * Dm + i];
        a3 += xv * rw[3 * Dm + i];
    }
    __shared__ float red[4][128];
    red[0][tid] = a0; red[1][tid] = a1; red[2][tid] = a2; red[3][tid] = a3;
    __syncthreads();
    for (int st = 64; st > 0; st >>= 1) {
        if (tid < st) {
            red[0][tid] += red[0][tid + st];
            red[1][tid] += red[1][tid + st];
            red[2][tid] += red[2][tid + st];
            red[3][tid] += red[3][tid + st];
        }
        __syncthreads();
    }
    if (tid == 0) {
        float g[4];
        float mx = -1e30f;
        for (int e = 0; e < 4; e++) { g[e] = red[e][0]; mx = fmaxf(mx, g[e]); }
        float ssum = 0.f;
        for (int e = 0; e < 4; e++) { g[e] = expf(g[e] - mx); ssum += g[e]; }
        float sinv = 1.f / ssum;
        for (int e = 0; e < 4; e++) g[e] *= sinv;
        int i1 = 0;
        for (int e = 1; e < 4; e++) if (g[e] > g[i1]) i1 = e;
        int i2 = -1;
        for (int e = 0; e < 4; e++) if (e != i1 && (i2 < 0 || g[e] > g[i2])) i2 = e;
        float sum2 = g[i1] + g[i2];
        if (sum2 < 1e-9f) sum2 = 1e-9f;
        float w1 = g[i1] / sum2, w2 = g[i2] / sum2;
        for (int e = 0; e < 4; e++) atomicAdd(&gatesum[e], g[e]);
        int p1 = atomicAdd(&icnt[i1], 1);
        idxbuf[i1 * Tt_ + p1] = t; gwbuf[i1 * Tt_ + p1] = w1;
        int p2 = atomicAdd(&icnt[i2], 1);
        idxbuf[i2 * Tt_ + p2] = t; gwbuf[i2 * Tt_ + p2] = w2;
    }
}

__global__ void k_aux(const float* __restrict__ gatesum, const int* __restrict__ icnt,
                      float* __restrict__ out, int out_size) {
    const int MAIN = Bc * Nn * Dm;
    if (out_size <= MAIN) return;
    float aux = 0.f;
    for (int e = 0; e < 4; e++)
        aux += (gatesum[e] / (float)Tt_) * ((float)icnt[e] / (float)Tt_);
    out[out_size - 1] = 4.f * aux;
}

__global__ void k_zero(int* __restrict__ icnt, float* __restrict__ gatesum) {
    int i = threadIdx.x;
    if (i < 8) icnt[i] = 0;
    if (i < 4) gatesum[i] = 0.f;
}

// ---------------- trend conv: k=5, zero pad 2, + bias ----------------------
__global__ void k_trend(const float* __restrict__ trt, const float* __restrict__ tw,
                        const float* __restrict__ tb, float* __restrict__ tt) {
    int d = blockIdx.x, b = blockIdx.y;
    int tid = threadIdx.x;
    __shared__ float row[Nn];
    const float* rp = trt + ((size_t)b * Dm + d) * Nn;
    for (int i = tid; i < Nn; i += blockDim.x) row[i] = rp[i];
    __syncthreads();
    float w[5];
#pragma unroll
    for (int j = 0; j < 5; j++) w[j] = tw[d * 5 + j];
    float bb = tb[d];
    float* op = tt + ((size_t)b * Dm + d) * Nn;
    for (int n = tid; n < Nn; n += blockDim.x) {
        float acc = bb;
#pragma unroll
        for (int j = 0; j < 5; j++) {
            int t = n - 2 + j;
            if (t >= 0 && t < Nn) acc += w[j] * row[t];
        }
        op[n] = acc;
    }
}

// ---------------- launch ---------------------------------------------------
extern "C" void kernel_launch(void* const* d_in, const int* in_sizes, int n_in,
                              void* d_out, int out_size) {
    const float* x = (const float*)d_in[0];
    const float* qw = (const float*)d_in[1];  const float* qb = (const float*)d_in[2];
    const float* kw_ = (const float*)d_in[3]; const float* kb = (const float*)d_in[4];
    const float* vw = (const float*)d_in[5];  const float* vb = (const float*)d_in[6];
    const float* ow = (const float*)d_in[7];  const float* ob = (const float*)d_in[8];
    const float* n1g = (const float*)d_in[9]; const float* n1b = (const float*)d_in[10];
    const float* n2g = (const float*)d_in[11]; const float* n2b = (const float*)d_in[12];
    const float* alpha = (const float*)d_in[13];
    const float* dw7 = (const float*)d_in[14];
    const float* dw25 = (const float*)d_in[15];
    const float* dw49 = (const float*)d_in[16];
    const float* router_w = (const float*)d_in[17];
    const float* ew1 = (const float*)d_in[18]; const float* eb1 = (const float*)d_in[19];
    const float* ew2 = (const float*)d_in[20]; const float* eb2 = (const float*)d_in[21];
    const float* tw = (const float*)d_in[22];  const float* tb = (const float*)d_in[23];
    float* out = (float*)d_out;

    float* sc; cudaGetSymbolAddress((void**)&sc, g_scratch);
    int* isc; cudaGetSymbolAddress((void**)&isc, g_iscratch);
    const size_t MM = (size_t)8 * 1024 * 1024;
    float* xt = sc;            float* trt = sc + MM;
    float* S  = sc + 2 * MM;   float* Sn  = sc + 3 * MM;
    float* q  = sc + 4 * MM;   float* kk  = sc + 5 * MM;
    float* vv = sc + 6 * MM;   float* y   = sc + 7 * MM;
    float* xs = sc + 8 * MM;   float* xf  = sc + 9 * MM;
    float* hbuf = sc + 10 * MM;
    float* tt = sc + 12 * MM;
    float* gwbuf = sc + 13 * MM;
    float* gatesum = sc + 13 * MM + 4 * Tt_;
    int* icnt = isc;
    int* idxbuf = isc + 64;

    dim3 tb32(32, 8);
    k_zero<<<1, 32>>>(icnt, gatesum);
    k_transpose<<<dim3(32, 32, Bc), tb32>>>(x, xt);
    k_decomp<<<dim3(Dm, Bc), 128>>>(xt, dw7, dw25, dw49, alpha, trt);
    k_makeS<<<dim3(32, 32, Bc), tb32>>>(x, trt, S);
    k_ln<<<Tt_, 256>>>(S, n1g, n1b, Sn);
    dim3 gqkv(Dm / 128, Tt_ / 128);
    k_sgemm<<<gqkv, 128>>>(Sn, qw, qb, nullptr, q, Tt_, nullptr, Dm, Dm, nullptr, nullptr, 0);
    k_sgemm<<<gqkv, 128>>>(Sn, kw_, kb, nullptr, kk, Tt_, nullptr, Dm, Dm, nullptr, nullptr, 0);
    k_sgemm<<<gqkv, 128>>>(Sn, vw, vb, nullptr, vv, Tt_, nullptr, Dm, Dm, nullptr, nullptr, 0);
    k_attn<<<dim3(Nn / 64, Hh, Bc), 128>>>(q, kk, vv, y);
    k_sgemm<<<gqkv, 128>>>(y, ow, ob, S, xs, Tt_, nullptr, Dm, Dm, nullptr, nullptr, 0);
    k_ln<<<Tt_, 256>>>(xs, n2g, n2b, xf);
    k_router<<<Tt_, 128>>>(xf, router_w, gatesum, icnt, idxbuf, gwbuf);
    k_aux<<<1, 1>>>(gatesum, icnt, out, out_size);
    for (int e = 0; e < NE; e++) {
        k_sgemm<<<dim3(MH / 128, Tt_ / 128), 128>>>(
            xf, ew1 + (size_t)e * MH * Dm, eb1 + e * MH, nullptr, hbuf,
            0, &icnt[e], MH, Dm, idxbuf + e * Tt_, nullptr, 1);
        k_sgemm<<<dim3(Dm / 128, Tt_ / 128), 128>>>(
            hbuf, ew2 + (size_t)e * Dm * MH, eb2 + e * Dm, nullptr, xs,
            0, &icnt[e], Dm, MH, idxbuf + e * Tt_, gwbuf + e * Tt_, 0);
    }
    k_trend<<<dim3(Dm, Bc), 128>>>(trt, tw, tb, tt);
    k_final<<<dim3(32, 32, Bc), tb32>>>(xs, tt, out);
}

// round 9
// speedup vs baseline: 1.1732x; 1.1732x over previous
#include <cuda_runtime.h>
#include <math.h>
#include <stdint.h>

#define Bc 8
#define Nn 1024
#define Dm 1024
#define Hh 16
#define HD 64
#define Tt_ 8192
#define NE 4
#define MH 2048

// ---------------- scratch (static device allocations only) ----------------
__device__ __align__(16) float g_scratch[(size_t)14 * 8 * 1024 * 1024];
__device__ int g_iscratch[64 + NE * Tt_];

// ---------------- transpose: in [B][R=1024][C=1024] -> out [B][C][R] --------
__global__ void k_transpose(const float* __restrict__ in, float* __restrict__ out) {
    __shared__ float tile[32][33];
    int b = blockIdx.z;
    int c0 = blockIdx.x * 32, r0 = blockIdx.y * 32;
    const float* ip = in + (size_t)b * Nn * Dm;
    float* op = out + (size_t)b * Nn * Dm;
    int tx = threadIdx.x, ty = threadIdx.y;
#pragma unroll
    for (int i = 0; i < 32; i += 8)
        tile[ty + i][tx] = ip[(size_t)(r0 + ty + i) * Dm + c0 + tx];
    __syncthreads();
#pragma unroll
    for (int i = 0; i < 32; i += 8)
        op[(size_t)(c0 + ty + i) * Nn + r0 + tx] = tile[tx][ty + i];
}

// ---------------- decomposition: 3 depthwise reflect convs, softmax-mixed ---
__global__ void k_decomp(const float* __restrict__ xt, const float* __restrict__ dw7,
                         const float* __restrict__ dw25, const float* __restrict__ dw49,
                         const float* __restrict__ alpha, float* __restrict__ trt) {
    int d = blockIdx.x, b = blockIdx.y;
    __shared__ float row[Nn];
    __shared__ float kw[96];
    int tid = threadIdx.x;
    const float* xr = xt + ((size_t)b * Dm + d) * Nn;
    for (int i = tid; i < Nn; i += blockDim.x) row[i] = xr[i];
    if (tid < 7) kw[tid] = dw7[d * 7 + tid];
    if (tid < 25) kw[7 + tid] = dw25[d * 25 + tid];
    if (tid < 49) kw[32 + tid] = dw49[d * 49 + tid];
    __syncthreads();
    float a0 = alpha[0], a1 = alpha[1], a2 = alpha[2];
    float mx = fmaxf(a0, fmaxf(a1, a2));
    float e0 = expf(a0 - mx), e1 = expf(a1 - mx), e2 = expf(a2 - mx);
    float inv = 1.f / (e0 + e1 + e2);
    float w0 = e0 * inv, w1 = e1 * inv, w2 = e2 * inv;
    float* out = trt + ((size_t)b * Dm + d) * Nn;
    for (int n = tid; n < Nn; n += blockDim.x) {
        float acc = 0.f;
#pragma unroll
        for (int j = 0; j < 7; j++) {
            int t = n - 3 + j; t = t < 0 ? -t : (t >= Nn ? 2 * (Nn - 1) - t : t);
            acc += w0 * kw[j] * row[t];
        }
#pragma unroll
        for (int j = 0; j < 25; j++) {
            int t = n - 12 + j; t = t < 0 ? -t : (t >= Nn ? 2 * (Nn - 1) - t : t);
            acc += w1 * kw[7 + j] * row[t];
        }
#pragma unroll
        for (int j = 0; j < 49; j++) {
            int t = n - 24 + j; t = t < 0 ? -t : (t >= Nn ? 2 * (Nn - 1) - t : t);
            acc += w2 * kw[32 + j] * row[t];
        }
        out[n] = acc;
    }
}

// ---------------- S[b,n,d] = x[b,n,d] - Trt[b,d,n] (tiled transpose-sub) ----
__global__ void k_makeS(const float* __restrict__ x, const float* __restrict__ trt,
                        float* __restrict__ S) {
    __shared__ float tile[32][33];
    int b = blockIdx.z;
    int d0 = blockIdx.x * 32, n0 = blockIdx.y * 32;
    int tx = threadIdx.x, ty = threadIdx.y;
#pragma unroll
    for (int i = 0; i < 32; i += 8)
        tile[ty + i][tx] = trt[(size_t)b * Dm * Nn + (size_t)(d0 + ty + i) * Nn + n0 + tx];
    __syncthreads();
#pragma unroll
    for (int i = 0; i < 32; i += 8) {
        size_t idx = (size_t)b * Nn * Dm + (size_t)(n0 + ty + i) * Dm + d0 + tx;
        S[idx] = x[idx] - tile[tx][ty + i];
    }
}

// ---------------- out[b,n,d] = xs[b,n,d] + Tt[b,d,n] ------------------------
__global__ void k_final(const float* __restrict__ xs, const float* __restrict__ tt,
                        float* __restrict__ out) {
    __shared__ float tile[32][33];
    int b = blockIdx.z;
    int d0 = blockIdx.x * 32, n0 = blockIdx.y * 32;
    int tx = threadIdx.x, ty = threadIdx.y;
#pragma unroll
    for (int i = 0; i < 32; i += 8)
        tile[ty + i][tx] = tt[(size_t)b * Dm * Nn + (size_t)(d0 + ty + i) * Nn + n0 + tx];
    __syncthreads();
#pragma unroll
    for (int i = 0; i < 32; i += 8) {
        size_t idx = (size_t)b * Nn * Dm + (size_t)(n0 + ty + i) * Dm + d0 + tx;
        out[idx] = xs[idx] + tile[tx][ty + i];
    }
}

// ---------------- layernorm over last dim (1024) ---------------------------
__global__ void k_ln(const float* __restrict__ x, const float* __restrict__ g,
                     const float* __restrict__ bta, float* __restrict__ out) {
    int row = blockIdx.x;
    int tid = threadIdx.x;
    const float* xr = x + (size_t)row * Dm;
    __shared__ float red[256];
    float s = 0.f;
    for (int i = tid; i < Dm; i += 256) s += xr[i];
    red[tid] = s; __syncthreads();
    for (int st = 128; st > 0; st >>= 1) { if (tid < st) red[tid] += red[tid + st]; __syncthreads(); }
    float mean = red[0] / Dm;
    __syncthreads();
    float v = 0.f;
    for (int i = tid; i < Dm; i += 256) { float dd = xr[i] - mean; v += dd * dd; }
    red[tid] = v; __syncthreads();
    for (int st = 128; st > 0; st >>= 1) { if (tid < st) red[tid] += red[tid + st]; __syncthreads(); }
    float inv = rsqrtf(red[0] / Dm + 1e-5f);
    for (int i = tid; i < Dm; i += 256)
        out[(size_t)row * Dm + i] = (xr[i] - mean) * inv * g[i] + bta[i];
}

// ---------------- TF32 tensor-core NT GEMM: C = A[M,K]*Bm[N,K]^T + bias -----
// R5 shape (256 thr, 8 warps, 32x64 warp tiles) + 3-stage cp.async pipeline.
// tf32 operands fed as raw fp32 bits (HW truncates low mantissa).
__device__ __forceinline__ void mma_tf32(float c[4], const uint32_t a[4], const uint32_t b[2]) {
    asm volatile(
        "mma.sync.aligned.m16n8k8.row.col.f32.tf32.tf32.f32 "
        "{%0,%1,%2,%3},{%4,%5,%6,%7},{%8,%9},{%0,%1,%2,%3};"
        : "+f"(c[0]), "+f"(c[1]), "+f"(c[2]), "+f"(c[3])
        : "r"(a[0]), "r"(a[1]), "r"(a[2]), "r"(a[3]), "r"(b[0]), "r"(b[1]));
}

__device__ __forceinline__ void cpa16(uint32_t dst, const float* src) {
    asm volatile("cp.async.cg.shared.global [%0], [%1], 16;" :: "r"(dst), "l"(src));
}
#define CP_COMMIT() asm volatile("cp.async.commit_group;" ::: "memory")
#define CP_WAIT2()  asm volatile("cp.async.wait_group 2;" ::: "memory")

#define SMS 20   // smem row stride (floats); banks 20q+r all-distinct mod 32
#define STG 3
#define SG_BYTES (2 * STG * 128 * SMS * 4)

__global__ void __launch_bounds__(256) k_sgemm(
    const float* __restrict__ A, const float* __restrict__ Bm,
    const float* __restrict__ bias, const float* __restrict__ res,
    float* __restrict__ C, int M, const int* __restrict__ Mdev,
    int Npar, int K, const int* __restrict__ gidx,
    const float* __restrict__ gscale, int gelu_flag) {
    if (Mdev) M = *Mdev;
    int bm = blockIdx.y * 128, bn = blockIdx.x * 128;
    if (bm >= M) return;
    extern __shared__ float dyn[];
    float* As = dyn;                       // [STG*128][SMS]
    float* Bs = dyn + STG * 128 * SMS;     // [STG*128][SMS]
    int tid = threadIdx.x;
    int warp = tid >> 5, lane = tid & 31;
    int wm = (warp & 3) * 32, wn = (warp >> 2) * 64;
    int qd = lane >> 2, rr = lane & 3;

    float c[2][8][4];
#pragma unroll
    for (int i = 0; i < 2; i++)
#pragma unroll
        for (int j = 0; j < 8; j++)
#pragma unroll
            for (int l = 0; l < 4; l++) c[i][j][l] = 0.f;

    int lrow = tid >> 1;
    int lk = (tid & 1) * 8;
    int am = bm + lrow;
    bool av = am < M;
    int asrc = av ? ((gidx && !gscale) ? gidx[am] : am) : 0;  // clamp; garbage rows discarded
    const float* Ap = A + (size_t)asrc * K + lk;
    const float* Bp = Bm + (size_t)(bn + lrow) * K + lk;

    uint32_t aDst = (uint32_t)__cvta_generic_to_shared(&As[lrow * SMS + lk]);
    uint32_t bDst = (uint32_t)__cvta_generic_to_shared(&Bs[lrow * SMS + lk]);
    const uint32_t stStride = 128 * SMS * 4;

    int ntiles = K >> 4;
    // prologue: stages 0,1
#pragma unroll
    for (int p = 0; p < 2; p++) {
        cpa16(aDst + p * stStride, Ap + p * 16);
        cpa16(aDst + p * stStride + 16, Ap + p * 16 + 4);
        cpa16(bDst + p * stStride, Bp + p * 16);
        cpa16(bDst + p * stStride + 16, Bp + p * 16 + 4);
        CP_COMMIT();
    }

    for (int kt = 0; kt < ntiles; kt++) {
        if (kt + 2 < ntiles) {
            int st = (kt + 2) % STG;
            const float* ap = Ap + (size_t)(kt + 2) * 16;
            const float* bp = Bp + (size_t)(kt + 2) * 16;
            cpa16(aDst + st * stStride, ap);
            cpa16(aDst + st * stStride + 16, ap + 4);
            cpa16(bDst + st * stStride, bp);
            cpa16(bDst + st * stStride + 16, bp + 4);
        }
        CP_COMMIT();
        CP_WAIT2();
        __syncthreads();
        int buf = kt % STG;
        const float* Ab = As + buf * 128 * SMS;
        const float* Bb = Bs + buf * 128 * SMS;
#pragma unroll
        for (int ks = 0; ks < 2; ks++) {
            int k0 = ks * 8;
            uint32_t af[2][4];
#pragma unroll
            for (int mi = 0; mi < 2; mi++) {
                int rb = wm + mi * 16;
                af[mi][0] = __float_as_uint(Ab[(rb + qd) * SMS + k0 + rr]);
                af[mi][1] = __float_as_uint(Ab[(rb + qd + 8) * SMS + k0 + rr]);
                af[mi][2] = __float_as_uint(Ab[(rb + qd) * SMS + k0 + rr + 4]);
                af[mi][3] = __float_as_uint(Ab[(rb + qd + 8) * SMS + k0 + rr + 4]);
            }
            uint32_t bf[8][2];
#pragma unroll
            for (int ni = 0; ni < 8; ni++) {
                int cb = wn + ni * 8 + qd;
                bf[ni][0] = __float_as_uint(Bb[cb * SMS + k0 + rr]);
                bf[ni][1] = __float_as_uint(Bb[cb * SMS + k0 + rr + 4]);
            }
#pragma unroll
            for (int mi = 0; mi < 2; mi++)
#pragma unroll
                for (int ni = 0; ni < 8; ni++)
                    mma_tf32(c[mi][ni], af[mi], bf[ni]);
        }
        __syncthreads();
    }

    // epilogue
#pragma unroll
    for (int mi = 0; mi < 2; mi++) {
#pragma unroll
        for (int hf = 0; hf < 2; hf++) {
            int m = bm + wm + mi * 16 + qd + hf * 8;
            if (m >= M) continue;
            int cr = gscale ? gidx[m] : m;
            float scv = gscale ? gscale[m] : 1.f;
            float* Crow = C + (size_t)cr * Npar;
            const float* Rrow = res ? res + (size_t)m * Npar : nullptr;
#pragma unroll
            for (int ni = 0; ni < 8; ni++) {
                int n = bn + wn + ni * 8 + 2 * rr;
                float v0 = c[mi][ni][hf * 2 + 0] + (bias ? bias[n] : 0.f);
                float v1 = c[mi][ni][hf * 2 + 1] + (bias ? bias[n + 1] : 0.f);
                if (gelu_flag) {
                    v0 = 0.5f * v0 * (1.f + erff(v0 * 0.70710678118654752f));
                    v1 = 0.5f * v1 * (1.f + erff(v1 * 0.70710678118654752f));
                }
                if (gscale) {
                    Crow[n] += v0 * scv;
                    Crow[n + 1] += v1 * scv;
                } else {
                    Crow[n] = v0 + (Rrow ? Rrow[n] : 0.f);
                    Crow[n + 1] = v1 + (Rrow ? Rrow[n + 1] : 0.f);
                }
            }
        }
    }
}

// ---------------- flash-style ALiBi attention (2 lanes per query) ----------
__global__ void __launch_bounds__(128) k_attn(const float* __restrict__ q,
                                              const float* __restrict__ k,
                                              const float* __restrict__ v,
                                              float* __restrict__ y) {
    int qt = blockIdx.x, h = blockIdx.y, b = blockIdx.z;
    int t = threadIdx.x;
    int qi = qt * 64 + (t >> 1);
    int half = (t & 1) * 32;
    __shared__ float Ks[64][64];
    __shared__ float Vs[64][64];
    float qr[32];
    const float* qp = q + ((size_t)(b * Nn + qi) * Dm + h * HD + half);
#pragma unroll
    for (int c = 0; c < 32; c += 4) {
        float4 f = *(const float4*)(qp + c);
        qr[c] = f.x; qr[c + 1] = f.y; qr[c + 2] = f.z; qr[c + 3] = f.w;
    }
    float o[32];
#pragma unroll
    for (int c = 0; c < 32; c++) o[c] = 0.f;
    float m = -1e30f, l = 0.f;
    float slope = exp2f(-0.5f * (float)(h + 1));
    for (int c0 = 0; c0 < Nn; c0 += 64) {
        for (int idx = t; idx < 64 * 64; idx += 128) {
            int row = idx >> 6, col = idx & 63;
            size_t base = ((size_t)(b * Nn + c0 + row) * Dm + h * HD);
            Ks[row][col] = k[base + col];
            Vs[row][col] = v[base + col];
        }
        __syncthreads();
        for (int j = 0; j < 64; j++) {
            float s0 = 0.f, s1 = 0.f, s2 = 0.f, s3 = 0.f;
            const float* kr = &Ks[j][half];
#pragma unroll
            for (int c = 0; c < 32; c += 4) {
                s0 += qr[c] * kr[c];
                s1 += qr[c + 1] * kr[c + 1];
                s2 += qr[c + 2] * kr[c + 2];
                s3 += qr[c + 3] * kr[c + 3];
            }
            float s = s0 + s1 + s2 + s3;
            s += __shfl_xor_sync(0xffffffffu, s, 1);
            s *= 0.125f;
            int dj = (c0 + j) - qi;
            if (dj > 0) s -= slope * (float)dj;
            float mn = fmaxf(m, s);
            float p = expf(s - mn);
            if (mn > m) {
                float corr = expf(m - mn);
                l *= corr;
#pragma unroll
                for (int c = 0; c < 32; c++) o[c] *= corr;
            }
            m = mn;
            l += p;
            const float* vr = &Vs[j][half];
#pragma unroll
            for (int c = 0; c < 32; c++) o[c] += p * vr[c];
        }
        __syncthreads();
    }
    float invl = 1.f / l;
    float* yp = y + ((size_t)(b * Nn + qi) * Dm + h * HD + half);
#pragma unroll
    for (int c = 0; c < 32; c++) yp[c] = o[c] * invl;
}

// ---------------- router: softmax gates, top-2, expert lists, aux sums -----
__global__ void k_router(const float* __restrict__ xf, const float* __restrict__ rw,
                         float* __restrict__ gatesum, int* __restrict__ icnt,
                         int* __restrict__ idxbuf, float* __restrict__ gwbuf) {
    int t = blockIdx.x;
    int tid = threadIdx.x;  // 128
    const float* xr = xf + (size_t)t * Dm;
    float a0 = 0.f, a1 = 0.f, a2 = 0.f, a3 = 0.f;
    for (int i = tid; i < Dm; i += 128) {
        float xv = xr[i];
        a0 += xv * rw[i];
        a1 += xv * rw[Dm + i];
        a2 += xv * rw[2 * Dm + i];
        a3 += xv * rw[3 * Dm + i];
    }
    __shared__ float red[4][128];
    red[0][tid] = a0; red[1][tid] = a1; red[2][tid] = a2; red[3][tid] = a3;
    __syncthreads();
    for (int st = 64; st > 0; st >>= 1) {
        if (tid < st) {
            red[0][tid] += red[0][tid + st];
            red[1][tid] += red[1][tid + st];
            red[2][tid] += red[2][tid + st];
            red[3][tid] += red[3][tid + st];
        }
        __syncthreads();
    }
    if (tid == 0) {
        float g[4];
        float mx = -1e30f;
        for (int e = 0; e < 4; e++) { g[e] = red[e][0]; mx = fmaxf(mx, g[e]); }
        float ssum = 0.f;
        for (int e = 0; e < 4; e++) { g[e] = expf(g[e] - mx); ssum += g[e]; }
        float sinv = 1.f / ssum;
        for (int e = 0; e < 4; e++) g[e] *= sinv;
        int i1 = 0;
        for (int e = 1; e < 4; e++) if (g[e] > g[i1]) i1 = e;
        int i2 = -1;
        for (int e = 0; e < 4; e++) if (e != i1 && (i2 < 0 || g[e] > g[i2])) i2 = e;
        float sum2 = g[i1] + g[i2];
        if (sum2 < 1e-9f) sum2 = 1e-9f;
        float w1 = g[i1] / sum2, w2 = g[i2] / sum2;
        for (int e = 0; e < 4; e++) atomicAdd(&gatesum[e], g[e]);
        int p1 = atomicAdd(&icnt[i1], 1);
        idxbuf[i1 * Tt_ + p1] = t; gwbuf[i1 * Tt_ + p1] = w1;
        int p2 = atomicAdd(&icnt[i2], 1);
        idxbuf[i2 * Tt_ + p2] = t; gwbuf[i2 * Tt_ + p2] = w2;
    }
}

__global__ void k_aux(const float* __restrict__ gatesum, const int* __restrict__ icnt,
                      float* __restrict__ out, int out_size) {
    const int MAIN = Bc * Nn * Dm;
    if (out_size <= MAIN) return;
    float aux = 0.f;
    for (int e = 0; e < 4; e++)
        aux += (gatesum[e] / (float)Tt_) * ((float)icnt[e] / (float)Tt_);
    out[out_size - 1] = 4.f * aux;
}

__global__ void k_zero(int* __restrict__ icnt, float* __restrict__ gatesum) {
    int i = threadIdx.x;
    if (i < 8) icnt[i] = 0;
    if (i < 4) gatesum[i] = 0.f;
}

// ---------------- trend conv: k=5, zero pad 2, + bias ----------------------
__global__ void k_trend(const float* __restrict__ trt, const float* __restrict__ tw,
                        const float* __restrict__ tb, float* __restrict__ tt) {
    int d = blockIdx.x, b = blockIdx.y;
    int tid = threadIdx.x;
    __shared__ float row[Nn];
    const float* rp = trt + ((size_t)b * Dm + d) * Nn;
    for (int i = tid; i < Nn; i += blockDim.x) row[i] = rp[i];
    __syncthreads();
    float w[5];
#pragma unroll
    for (int j = 0; j < 5; j++) w[j] = tw[d * 5 + j];
    float bb = tb[d];
    float* op = tt + ((size_t)b * Dm + d) * Nn;
    for (int n = tid; n < Nn; n += blockDim.x) {
        float acc = bb;
#pragma unroll
        for (int j = 0; j < 5; j++) {
            int t = n - 2 + j;
            if (t >= 0 && t < Nn) acc += w[j] * row[t];
        }
        op[n] = acc;
    }
}

// ---------------- launch ---------------------------------------------------
extern "C" void kernel_launch(void* const* d_in, const int* in_sizes, int n_in,
                              void* d_out, int out_size) {
    const float* x = (const float*)d_in[0];
    const float* qw = (const float*)d_in[1];  const float* qb = (const float*)d_in[2];
    const float* kw_ = (const float*)d_in[3]; const float* kb = (const float*)d_in[4];
    const float* vw = (const float*)d_in[5];  const float* vb = (const float*)d_in[6];
    const float* ow = (const float*)d_in[7];  const float* ob = (const float*)d_in[8];
    const float* n1g = (const float*)d_in[9]; const float* n1b = (const float*)d_in[10];
    const float* n2g = (const float*)d_in[11]; const float* n2b = (const float*)d_in[12];
    const float* alpha = (const float*)d_in[13];
    const float* dw7 = (const float*)d_in[14];
    const float* dw25 = (const float*)d_in[15];
    const float* dw49 = (const float*)d_in[16];
    const float* router_w = (const float*)d_in[17];
    const float* ew1 = (const float*)d_in[18]; const float* eb1 = (const float*)d_in[19];
    const float* ew2 = (const float*)d_in[20]; const float* eb2 = (const float*)d_in[21];
    const float* tw = (const float*)d_in[22];  const float* tb = (const float*)d_in[23];
    float* out = (float*)d_out;

    float* sc; cudaGetSymbolAddress((void**)&sc, g_scratch);
    int* isc; cudaGetSymbolAddress((void**)&isc, g_iscratch);
    const size_t MM = (size_t)8 * 1024 * 1024;
    float* xt = sc;            float* trt = sc + MM;
    float* S  = sc + 2 * MM;   float* Sn  = sc + 3 * MM;
    float* q  = sc + 4 * MM;   float* kk  = sc + 5 * MM;
    float* vv = sc + 6 * MM;   float* y   = sc + 7 * MM;
    float* xs = sc + 8 * MM;   float* xf  = sc + 9 * MM;
    float* hbuf = sc + 10 * MM;
    float* tt = sc + 12 * MM;
    float* gwbuf = sc + 13 * MM;
    float* gatesum = sc + 13 * MM + 4 * Tt_;
    int* icnt = isc;
    int* idxbuf = isc + 64;

    static int smem_set = 0;
    if (!smem_set) {
        cudaFuncSetAttribute(k_sgemm, cudaFuncAttributeMaxDynamicSharedMemorySize, SG_BYTES);
        smem_set = 1;
    }

    dim3 tb32(32, 8);
    k_zero<<<1, 32>>>(icnt, gatesum);
    k_transpose<<<dim3(32, 32, Bc), tb32>>>(x, xt);
    k_decomp<<<dim3(Dm, Bc), 128>>>(xt, dw7, dw25, dw49, alpha, trt);
    k_makeS<<<dim3(32, 32, Bc), tb32>>>(x, trt, S);
    k_ln<<<Tt_, 256>>>(S, n1g, n1b, Sn);
    dim3 gqkv(Dm / 128, Tt_ / 128);
    k_sgemm<<<gqkv, 256, SG_BYTES>>>(Sn, qw, qb, nullptr, q, Tt_, nullptr, Dm, Dm, nullptr, nullptr, 0);
    k_sgemm<<<gqkv, 256, SG_BYTES>>>(Sn, kw_, kb, nullptr, kk, Tt_, nullptr, Dm, Dm, nullptr, nullptr, 0);
    k_sgemm<<<gqkv, 256, SG_BYTES>>>(Sn, vw, vb, nullptr, vv, Tt_, nullptr, Dm, Dm, nullptr, nullptr, 0);
    k_attn<<<dim3(Nn / 64, Hh, Bc), 128>>>(q, kk, vv, y);
    k_sgemm<<<gqkv, 256, SG_BYTES>>>(y, ow, ob, S, xs, Tt_, nullptr, Dm, Dm, nullptr, nullptr, 0);
    k_ln<<<Tt_, 256>>>(xs, n2g, n2b, xf);
    k_router<<<Tt_, 128>>>(xf, router_w, gatesum, icnt, idxbuf, gwbuf);
    k_aux<<<1, 1>>>(gatesum, icnt, out, out_size);
    for (int e = 0; e < NE; e++) {
        k_sgemm<<<dim3(MH / 128, Tt_ / 128), 256, SG_BYTES>>>(
            xf, ew1 + (size_t)e * MH * Dm, eb1 + e * MH, nullptr, hbuf,
            0, &icnt[e], MH, Dm, idxbuf + e * Tt_, nullptr, 1);
        k_sgemm<<<dim3(Dm / 128, Tt_ / 128), 256, SG_BYTES>>>(
            hbuf, ew2 + (size_t)e * Dm * MH, eb2 + e * Dm, nullptr, xs,
            0, &icnt[e], Dm, MH, idxbuf + e * Tt_, gwbuf + e * Tt_, 0);
    }
    k_trend<<<dim3(Dm, Bc), 128>>>(trt, tw, tb, tt);
    k_final<<<dim3(32, 32, Bc), tb32>>>(xs, tt, out);
}

// round 13
// speedup vs baseline: 1.1794x; 1.0053x over previous
#include <cuda_runtime.h>
#include <math.h>
#include <stdint.h>

#define Bc 8
#define Nn 1024
#define Dm 1024
#define Hh 16
#define HD 64
#define Tt_ 8192
#define NE 4
#define MH 2048

// ---------------- scratch (static device allocations only) ----------------
__device__ __align__(16) float g_scratch[(size_t)17 * 8 * 1024 * 1024];
__device__ int g_iscratch[64 + NE * Tt_];

__device__ __forceinline__ float cvt1_tf32(float v) {
    uint32_t u;
    asm("cvt.rna.tf32.f32 %0,%1;" : "=r"(u) : "f"(v));
    return __uint_as_float(u);
}
__device__ __forceinline__ float4 cvt4_tf32(float4 v) {
    v.x = cvt1_tf32(v.x); v.y = cvt1_tf32(v.y);
    v.z = cvt1_tf32(v.z); v.w = cvt1_tf32(v.w);
    return v;
}

// ---------------- round weights to tf32 (rna) into scratch -----------------
__global__ void k_cvt(const float4* __restrict__ in, float4* __restrict__ out, int n4) {
    int i = blockIdx.x * blockDim.x + threadIdx.x;
    if (i < n4) out[i] = cvt4_tf32(in[i]);
}

// ---------------- transpose: in [B][R=1024][C=1024] -> out [B][C][R] --------
__global__ void k_transpose(const float* __restrict__ in, float* __restrict__ out) {
    __shared__ float tile[32][33];
    int b = blockIdx.z;
    int c0 = blockIdx.x * 32, r0 = blockIdx.y * 32;
    const float* ip = in + (size_t)b * Nn * Dm;
    float* op = out + (size_t)b * Nn * Dm;
    int tx = threadIdx.x, ty = threadIdx.y;
#pragma unroll
    for (int i = 0; i < 32; i += 8)
        tile[ty + i][tx] = ip[(size_t)(r0 + ty + i) * Dm + c0 + tx];
    __syncthreads();
#pragma unroll
    for (int i = 0; i < 32; i += 8)
        op[(size_t)(c0 + ty + i) * Nn + r0 + tx] = tile[tx][ty + i];
}

// ---------------- decomposition: 3 depthwise reflect convs, softmax-mixed ---
__global__ void k_decomp(const float* __restrict__ xt, const float* __restrict__ dw7,
                         const float* __restrict__ dw25, const float* __restrict__ dw49,
                         const float* __restrict__ alpha, float* __restrict__ trt) {
    int d = blockIdx.x, b = blockIdx.y;
    __shared__ float row[Nn];
    __shared__ float kw[96];
    int tid = threadIdx.x;
    const float* xr = xt + ((size_t)b * Dm + d) * Nn;
    for (int i = tid; i < Nn; i += blockDim.x) row[i] = xr[i];
    if (tid < 7) kw[tid] = dw7[d * 7 + tid];
    if (tid < 25) kw[7 + tid] = dw25[d * 25 + tid];
    if (tid < 49) kw[32 + tid] = dw49[d * 49 + tid];
    __syncthreads();
    float a0 = alpha[0], a1 = alpha[1], a2 = alpha[2];
    float mx = fmaxf(a0, fmaxf(a1, a2));
    float e0 = expf(a0 - mx), e1 = expf(a1 - mx), e2 = expf(a2 - mx);
    float inv = 1.f / (e0 + e1 + e2);
    float w0 = e0 * inv, w1 = e1 * inv, w2 = e2 * inv;
    float* out = trt + ((size_t)b * Dm + d) * Nn;
    for (int n = tid; n < Nn; n += blockDim.x) {
        float acc = 0.f;
#pragma unroll
        for (int j = 0; j < 7; j++) {
            int t = n - 3 + j; t = t < 0 ? -t : (t >= Nn ? 2 * (Nn - 1) - t : t);
            acc += w0 * kw[j] * row[t];
        }
#pragma unroll
        for (int j = 0; j < 25; j++) {
            int t = n - 12 + j; t = t < 0 ? -t : (t >= Nn ? 2 * (Nn - 1) - t : t);
            acc += w1 * kw[7 + j] * row[t];
        }
#pragma unroll
        for (int j = 0; j < 49; j++) {
            int t = n - 24 + j; t = t < 0 ? -t : (t >= Nn ? 2 * (Nn - 1) - t : t);
            acc += w2 * kw[32 + j] * row[t];
        }
        out[n] = acc;
    }
}

// ---------------- S[b,n,d] = x[b,n,d] - Trt[b,d,n] (tiled transpose-sub) ----
__global__ void k_makeS(const float* __restrict__ x, const float* __restrict__ trt,
                        float* __restrict__ S) {
    __shared__ float tile[32][33];
    int b = blockIdx.z;
    int d0 = blockIdx.x * 32, n0 = blockIdx.y * 32;
    int tx = threadIdx.x, ty = threadIdx.y;
#pragma unroll
    for (int i = 0; i < 32; i += 8)
        tile[ty + i][tx] = trt[(size_t)b * Dm * Nn + (size_t)(d0 + ty + i) * Nn + n0 + tx];
    __syncthreads();
#pragma unroll
    for (int i = 0; i < 32; i += 8) {
        size_t idx = (size_t)b * Nn * Dm + (size_t)(n0 + ty + i) * Dm + d0 + tx;
        S[idx] = x[idx] - tile[tx][ty + i];
    }
}

// ---------------- out[b,n,d] = xs[b,n,d] + Tt[b,d,n] ------------------------
__global__ void k_final(const float* __restrict__ xs, const float* __restrict__ tt,
                        float* __restrict__ out) {
    __shared__ float tile[32][33];
    int b = blockIdx.z;
    int d0 = blockIdx.x * 32, n0 = blockIdx.y * 32;
    int tx = threadIdx.x, ty = threadIdx.y;
#pragma unroll
    for (int i = 0; i < 32; i += 8)
        tile[ty + i][tx] = tt[(size_t)b * Dm * Nn + (size_t)(d0 + ty + i) * Nn + n0 + tx];
    __syncthreads();
#pragma unroll
    for (int i = 0; i < 32; i += 8) {
        size_t idx = (size_t)b * Nn * Dm + (size_t)(n0 + ty + i) * Dm + d0 + tx;
        out[idx] = xs[idx] + tile[tx][ty + i];
    }
}

// ---------------- layernorm over last dim (1024), optional tf32 round ------
__global__ void k_ln(const float* __restrict__ x, const float* __restrict__ g,
                     const float* __restrict__ bta, float* __restrict__ out, int rnd) {
    int row = blockIdx.x;
    int tid = threadIdx.x;
    const float* xr = x + (size_t)row * Dm;
    __shared__ float red[256];
    float s = 0.f;
    for (int i = tid; i < Dm; i += 256) s += xr[i];
    red[tid] = s; __syncthreads();
    for (int st = 128; st > 0; st >>= 1) { if (tid < st) red[tid] += red[tid + st]; __syncthreads(); }
    float mean = red[0] / Dm;
    __syncthreads();
    float v = 0.f;
    for (int i = tid; i < Dm; i += 256) { float dd = xr[i] - mean; v += dd * dd; }
    red[tid] = v; __syncthreads();
    for (int st = 128; st > 0; st >>= 1) { if (tid < st) red[tid] += red[tid + st]; __syncthreads(); }
    float inv = rsqrtf(red[0] / Dm + 1e-5f);
    for (int i = tid; i < Dm; i += 256) {
        float vv = (xr[i] - mean) * inv * g[i] + bta[i];
        out[(size_t)row * Dm + i] = rnd ? cvt1_tf32(vv) : vv;
    }
}

// ---------------- TF32 tensor-core NT GEMM: C = A[M,K]*Bm[N,K]^T + bias -----
// 256 thr, 8 warps, 32x64 warp tiles, 3-stage cp.async pipeline.
// flags: bit0 = exact-erf GELU epilogue, bit1 = round stored C to tf32 (rna)
__device__ __forceinline__ void mma_tf32(float c[4], const uint32_t a[4], const uint32_t b[2]) {
    asm volatile(
        "mma.sync.aligned.m16n8k8.row.col.f32.tf32.tf32.f32 "
        "{%0,%1,%2,%3},{%4,%5,%6,%7},{%8,%9},{%0,%1,%2,%3};"
        : "+f"(c[0]), "+f"(c[1]), "+f"(c[2]), "+f"(c[3])
        : "r"(a[0]), "r"(a[1]), "r"(a[2]), "r"(a[3]), "r"(b[0]), "r"(b[1]));
}

__device__ __forceinline__ void cpa16(uint32_t dst, const float* src) {
    asm volatile("cp.async.cg.shared.global [%0], [%1], 16;" :: "r"(dst), "l"(src));
}
#define CP_COMMIT() asm volatile("cp.async.commit_group;" ::: "memory")
#define CP_WAIT2()  asm volatile("cp.async.wait_group 2;" ::: "memory")

#define SMS 20   // smem row stride (floats); banks 20q+r all-distinct mod 32
#define STG 3
#define SG_BYTES (2 * STG * 128 * SMS * 4)

__global__ void __launch_bounds__(256) k_sgemm(
    const float* __restrict__ A, const float* __restrict__ Bm,
    const float* __restrict__ bias, const float* __restrict__ res,
    float* __restrict__ C, int M, const int* __restrict__ Mdev,
    int Npar, int K, const int* __restrict__ gidx,
    const float* __restrict__ gscale, int flags) {
    if (Mdev) M = *Mdev;
    int bm = blockIdx.y * 128, bn = blockIdx.x * 128;
    if (bm >= M) return;
    extern __shared__ float dyn[];
    float* As = dyn;
    float* Bs = dyn + STG * 128 * SMS;
    int tid = threadIdx.x;
    int warp = tid >> 5, lane = tid & 31;
    int wm = (warp & 3) * 32, wn = (warp >> 2) * 64;
    int qd = lane >> 2, rr = lane & 3;

    float c[2][8][4];
#pragma unroll
    for (int i = 0; i < 2; i++)
#pragma unroll
        for (int j = 0; j < 8; j++)
#pragma unroll
            for (int l = 0; l < 4; l++) c[i][j][l] = 0.f;

    int lrow = tid >> 1;
    int lk = (tid & 1) * 8;
    int am = bm + lrow;
    bool av = am < M;
    int asrc = av ? ((gidx && !gscale) ? gidx[am] : am) : 0;
    const float* Ap = A + (size_t)asrc * K + lk;
    const float* Bp = Bm + (size_t)(bn + lrow) * K + lk;

    uint32_t aDst = (uint32_t)__cvta_generic_to_shared(&As[lrow * SMS + lk]);
    uint32_t bDst = (uint32_t)__cvta_generic_to_shared(&Bs[lrow * SMS + lk]);
    const uint32_t stStride = 128 * SMS * 4;

    int ntiles = K >> 4;
#pragma unroll
    for (int p = 0; p < 2; p++) {
        cpa16(aDst + p * stStride, Ap + p * 16);
        cpa16(aDst + p * stStride + 16, Ap + p * 16 + 4);
        cpa16(bDst + p * stStride, Bp + p * 16);
        cpa16(bDst + p * stStride + 16, Bp + p * 16 + 4);
        CP_COMMIT();
    }

    for (int kt = 0; kt < ntiles; kt++) {
        if (kt + 2 < ntiles) {
            int st = (kt + 2) % STG;
            const float* ap = Ap + (size_t)(kt + 2) * 16;
            const float* bp = Bp + (size_t)(kt + 2) * 16;
            cpa16(aDst + st * stStride, ap);
            cpa16(aDst + st * stStride + 16, ap + 4);
            cpa16(bDst + st * stStride, bp);
            cpa16(bDst + st * stStride + 16, bp + 4);
        }
        CP_COMMIT();
        CP_WAIT2();
        __syncthreads();
        int buf = kt % STG;
        const float* Ab = As + buf * 128 * SMS;
        const float* Bb = Bs + buf * 128 * SMS;
#pragma unroll
        for (int ks = 0; ks < 2; ks++) {
            int k0 = ks * 8;
            uint32_t af[2][4];
#pragma unroll
            for (int mi = 0; mi < 2; mi++) {
                int rb = wm + mi * 16;
                af[mi][0] = __float_as_uint(Ab[(rb + qd) * SMS + k0 + rr]);
                af[mi][1] = __float_as_uint(Ab[(rb + qd + 8) * SMS + k0 + rr]);
                af[mi][2] = __float_as_uint(Ab[(rb + qd) * SMS + k0 + rr + 4]);
                af[mi][3] = __float_as_uint(Ab[(rb + qd + 8) * SMS + k0 + rr + 4]);
            }
            uint32_t bf[8][2];
#pragma unroll
            for (int ni = 0; ni < 8; ni++) {
                int cb = wn + ni * 8 + qd;
                bf[ni][0] = __float_as_uint(Bb[cb * SMS + k0 + rr]);
                bf[ni][1] = __float_as_uint(Bb[cb * SMS + k0 + rr + 4]);
            }
#pragma unroll
            for (int mi = 0; mi < 2; mi++)
#pragma unroll
                for (int ni = 0; ni < 8; ni++)
                    mma_tf32(c[mi][ni], af[mi], bf[ni]);
        }
        __syncthreads();
    }

#pragma unroll
    for (int mi = 0; mi < 2; mi++) {
#pragma unroll
        for (int hf = 0; hf < 2; hf++) {
            int m = bm + wm + mi * 16 + qd + hf * 8;
            if (m >= M) continue;
            int cr = gscale ? gidx[m] : m;
            float scv = gscale ? gscale[m] : 1.f;
            float* Crow = C + (size_t)cr * Npar;
            const float* Rrow = res ? res + (size_t)m * Npar : nullptr;
#pragma unroll
            for (int ni = 0; ni < 8; ni++) {
                int n = bn + wn + ni * 8 + 2 * rr;
                float v0 = c[mi][ni][hf * 2 + 0] + (bias ? bias[n] : 0.f);
                float v1 = c[mi][ni][hf * 2 + 1] + (bias ? bias[n + 1] : 0.f);
                if (flags & 1) {
                    v0 = 0.5f * v0 * (1.f + erff(v0 * 0.70710678118654752f));
                    v1 = 0.5f * v1 * (1.f + erff(v1 * 0.70710678118654752f));
                }
                if (flags & 2) { v0 = cvt1_tf32(v0); v1 = cvt1_tf32(v1); }
                if (gscale) {
                    Crow[n] += v0 * scv;
                    Crow[n + 1] += v1 * scv;
                } else {
                    Crow[n] = v0 + (Rrow ? Rrow[n] : 0.f);
                    Crow[n + 1] = v1 + (Rrow ? Rrow[n + 1] : 0.f);
                }
            }
        }
    }
}

// ---------------- MMA flash attention with ALiBi ----------------------------
// block: 128 thr / 4 warps; one (b, h, 64-query tile). Warp owns 16 queries.
// S = Q*K^T and O += P*V via m16n8k8 tf32 MMA; online softmax on fragments.
__global__ void __launch_bounds__(128) k_attn(const float* __restrict__ q,
                                              const float* __restrict__ k,
                                              const float* __restrict__ v,
                                              float* __restrict__ y) {
    int qt = blockIdx.x, h = blockIdx.y, b = blockIdx.z;
    int tid = threadIdx.x, warp = tid >> 5, lane = tid & 31;
    int qd = lane >> 2, rr = lane & 3;
    int wq = warp * 16;
    int qbase = qt * 64;
    __shared__ float Ks[64][68];
    __shared__ float Vs[64][68];
    __shared__ float Ps[64][68];

    // cooperative Q tile load into Ps, then extract A fragments
    const size_t qoff = ((size_t)(b * Nn + qbase)) * Dm + h * HD;
    for (int idx = tid; idx < 64 * 16; idx += 128) {
        int row = idx >> 4, c4 = (idx & 15) * 4;
        float4 f = *(const float4*)(q + qoff + (size_t)row * Dm + c4);
        Ps[row][c4] = f.x; Ps[row][c4 + 1] = f.y;
        Ps[row][c4 + 2] = f.z; Ps[row][c4 + 3] = f.w;
    }
    __syncthreads();
    uint32_t qa[8][4];
#pragma unroll
    for (int kk = 0; kk < 8; kk++) {
        qa[kk][0] = __float_as_uint(Ps[wq + qd][kk * 8 + rr]);
        qa[kk][1] = __float_as_uint(Ps[wq + qd + 8][kk * 8 + rr]);
        qa[kk][2] = __float_as_uint(Ps[wq + qd][kk * 8 + rr + 4]);
        qa[kk][3] = __float_as_uint(Ps[wq + qd + 8][kk * 8 + rr + 4]);
    }

    float m0 = -1e30f, m1 = -1e30f, l0 = 0.f, l1 = 0.f;
    float o[8][4];
#pragma unroll
    for (int i = 0; i < 8; i++)
#pragma unroll
        for (int j = 0; j < 4; j++) o[i][j] = 0.f;
    float slope = exp2f(-0.5f * (float)(h + 1));
    int qi0 = qbase + wq + qd, qi1 = qi0 + 8;

    for (int c0 = 0; c0 < Nn; c0 += 64) {
        __syncthreads();  // previous-tile Ks/Vs reads done
        for (int idx = tid; idx < 64 * 16; idx += 128) {
            int row = idx >> 4, c4 = (idx & 15) * 4;
            size_t base = ((size_t)(b * Nn + c0 + row)) * Dm + h * HD + c4;
            float4 fk = *(const float4*)(k + base);
            float4 fv = *(const float4*)(v + base);
            Ks[row][c4] = fk.x; Ks[row][c4 + 1] = fk.y;
            Ks[row][c4 + 2] = fk.z; Ks[row][c4 + 3] = fk.w;
            Vs[row][c4] = fv.x; Vs[row][c4 + 1] = fv.y;
            Vs[row][c4 + 2] = fv.z; Vs[row][c4 + 3] = fv.w;
        }
        __syncthreads();

        // S = Q*K^T  (16 x 64 per warp)
        float s[8][4];
#pragma unroll
        for (int i = 0; i < 8; i++)
#pragma unroll
            for (int j = 0; j < 4; j++) s[i][j] = 0.f;
#pragma unroll
        for (int kk = 0; kk < 8; kk++) {
#pragma unroll
            for (int ni = 0; ni < 8; ni++) {
                uint32_t bb[2];
                bb[0] = __float_as_uint(Ks[ni * 8 + qd][kk * 8 + rr]);
                bb[1] = __float_as_uint(Ks[ni * 8 + qd][kk * 8 + rr + 4]);
                mma_tf32(s[ni], qa[kk], bb);
            }
        }
        // scale + alibi + row max
        float rmax0 = -1e30f, rmax1 = -1e30f;
#pragma unroll
        for (int ni = 0; ni < 8; ni++) {
            int j = c0 + ni * 8 + 2 * rr;
            s[ni][0] = s[ni][0] * 0.125f - slope * fmaxf(0.f, (float)(j - qi0));
            s[ni][1] = s[ni][1] * 0.125f - slope * fmaxf(0.f, (float)(j + 1 - qi0));
            s[ni][2] = s[ni][2] * 0.125f - slope * fmaxf(0.f, (float)(j - qi1));
            s[ni][3] = s[ni][3] * 0.125f - slope * fmaxf(0.f, (float)(j + 1 - qi1));
            rmax0 = fmaxf(rmax0, fmaxf(s[ni][0], s[ni][1]));
            rmax1 = fmaxf(rmax1, fmaxf(s[ni][2], s[ni][3]));
        }
        rmax0 = fmaxf(rmax0, __shfl_xor_sync(0xffffffffu, rmax0, 1));
        rmax0 = fmaxf(rmax0, __shfl_xor_sync(0xffffffffu, rmax0, 2));
        rmax1 = fmaxf(rmax1, __shfl_xor_sync(0xffffffffu, rmax1, 1));
        rmax1 = fmaxf(rmax1, __shfl_xor_sync(0xffffffffu, rmax1, 2));
        float nm0 = fmaxf(m0, rmax0), nm1 = fmaxf(m1, rmax1);
        float corr0 = expf(m0 - nm0), corr1 = expf(m1 - nm1);
        m0 = nm0; m1 = nm1;
        // p = exp(s - m), rounded to tf32 (P operand); l from rounded p
        float ls0 = 0.f, ls1 = 0.f;
#pragma unroll
        for (int ni = 0; ni < 8; ni++) {
            s[ni][0] = cvt1_tf32(expf(s[ni][0] - m0));
            s[ni][1] = cvt1_tf32(expf(s[ni][1] - m0));
            s[ni][2] = cvt1_tf32(expf(s[ni][2] - m1));
            s[ni][3] = cvt1_tf32(expf(s[ni][3] - m1));
            ls0 += s[ni][0] + s[ni][1];
            ls1 += s[ni][2] + s[ni][3];
        }
        ls0 += __shfl_xor_sync(0xffffffffu, ls0, 1);
        ls0 += __shfl_xor_sync(0xffffffffu, ls0, 2);
        ls1 += __shfl_xor_sync(0xffffffffu, ls1, 1);
        ls1 += __shfl_xor_sync(0xffffffffu, ls1, 2);
        l0 = l0 * corr0 + ls0;
        l1 = l1 * corr1 + ls1;
        // write P to warp-private smem strip (C-frag layout -> A-frag reload)
#pragma unroll
        for (int ni = 0; ni < 8; ni++) {
            Ps[wq + qd][ni * 8 + 2 * rr] = s[ni][0];
            Ps[wq + qd][ni * 8 + 2 * rr + 1] = s[ni][1];
            Ps[wq + qd + 8][ni * 8 + 2 * rr] = s[ni][2];
            Ps[wq + qd + 8][ni * 8 + 2 * rr + 1] = s[ni][3];
        }
        // rescale O
#pragma unroll
        for (int ni = 0; ni < 8; ni++) {
            o[ni][0] *= corr0; o[ni][1] *= corr0;
            o[ni][2] *= corr1; o[ni][3] *= corr1;
        }
        __syncwarp();
        // O += P*V : A = P (16 x 64 keys), B[k=key][n=hd] = Vs[key][hd]
#pragma unroll
        for (int kk = 0; kk < 8; kk++) {
            uint32_t pa[4];
            pa[0] = __float_as_uint(Ps[wq + qd][kk * 8 + rr]);
            pa[1] = __float_as_uint(Ps[wq + qd + 8][kk * 8 + rr]);
            pa[2] = __float_as_uint(Ps[wq + qd][kk * 8 + rr + 4]);
            pa[3] = __float_as_uint(Ps[wq + qd + 8][kk * 8 + rr + 4]);
#pragma unroll
            for (int ni = 0; ni < 8; ni++) {
                uint32_t bb[2];
                bb[0] = __float_as_uint(Vs[kk * 8 + rr][ni * 8 + qd]);
                bb[1] = __float_as_uint(Vs[kk * 8 + rr + 4][ni * 8 + qd]);
                mma_tf32(o[ni], pa, bb);
            }
        }
        __syncwarp();
    }

    float il0 = 1.f / l0, il1 = 1.f / l1;
    float* y0 = y + ((size_t)(b * Nn + qi0)) * Dm + h * HD;
    float* y1 = y + ((size_t)(b * Nn + qi1)) * Dm + h * HD;
#pragma unroll
    for (int ni = 0; ni < 8; ni++) {
        int n = ni * 8 + 2 * rr;
        y0[n] = cvt1_tf32(o[ni][0] * il0);
        y0[n + 1] = cvt1_tf32(o[ni][1] * il0);
        y1[n] = cvt1_tf32(o[ni][2] * il1);
        y1[n + 1] = cvt1_tf32(o[ni][3] * il1);
    }
}

// ---------------- router: softmax gates, top-2, expert lists, aux sums -----
__global__ void k_router(const float* __restrict__ xf, const float* __restrict__ rw,
                         float* __restrict__ gatesum, int* __restrict__ icnt,
                         int* __restrict__ idxbuf, float* __restrict__ gwbuf) {
    int t = blockIdx.x;
    int tid = threadIdx.x;  // 128
    const float* xr = xf + (size_t)t * Dm;
    float a0 = 0.f, a1 = 0.f, a2 = 0.f, a3 = 0.f;
    for (int i = tid; i < Dm; i += 128) {
        float xv = xr[i];
        a0 += xv * rw[i];
        a1 += xv * rw[Dm + i];
        a2 += xv * rw[2 * Dm + i];
        a3 += xv * rw[3 * Dm + i];
    }
    __shared__ float red[4][128];
    red[0][tid] = a0; red[1][tid] = a1; red[2][tid] = a2; red[3][tid] = a3;
    __syncthreads();
    for (int st = 64; st > 0; st >>= 1) {
        if (tid < st) {
            red[0][tid] += red[0][tid + st];
            red[1][tid] += red[1][tid + st];
            red[2][tid] += red[2][tid + st];
            red[3][tid] += red[3][tid + st];
        }
        __syncthreads();
    }
    if (tid == 0) {
        float g[4];
        float mx = -1e30f;
        for (int e = 0; e < 4; e++) { g[e] = red[e][0]; mx = fmaxf(mx, g[e]); }
        float ssum = 0.f;
        for (int e = 0; e < 4; e++) { g[e] = expf(g[e] - mx); ssum += g[e]; }
        float sinv = 1.f / ssum;
        for (int e = 0; e < 4; e++) g[e] *= sinv;
        int i1 = 0;
        for (int e = 1; e < 4; e++) if (g[e] > g[i1]) i1 = e;
        int i2 = -1;
        for (int e = 0; e < 4; e++) if (e != i1 && (i2 < 0 || g[e] > g[i2])) i2 = e;
        float sum2 = g[i1] + g[i2];
        if (sum2 < 1e-9f) sum2 = 1e-9f;
        float w1 = g[i1] / sum2, w2 = g[i2] / sum2;
        for (int e = 0; e < 4; e++) atomicAdd(&gatesum[e], g[e]);
        int p1 = atomicAdd(&icnt[i1], 1);
        idxbuf[i1 * Tt_ + p1] = t; gwbuf[i1 * Tt_ + p1] = w1;
        int p2 = atomicAdd(&icnt[i2], 1);
        idxbuf[i2 * Tt_ + p2] = t; gwbuf[i2 * Tt_ + p2] = w2;
    }
}

__global__ void k_aux(const float* __restrict__ gatesum, const int* __restrict__ icnt,
                      float* __restrict__ out, int out_size) {
    const int MAIN = Bc * Nn * Dm;
    if (out_size <= MAIN) return;
    float aux = 0.f;
    for (int e = 0; e < 4; e++)
        aux += (gatesum[e] / (float)Tt_) * ((float)icnt[e] / (float)Tt_);
    out[out_size - 1] = 4.f * aux;
}

__global__ void k_zero(int* __restrict__ icnt, float* __restrict__ gatesum) {
    int i = threadIdx.x;
    if (i < 8) icnt[i] = 0;
    if (i < 4) gatesum[i] = 0.f;
}

// ---------------- trend conv: k=5, zero pad 2, + bias ----------------------
__global__ void k_trend(const float* __restrict__ trt, const float* __restrict__ tw,
                        const float* __restrict__ tb, float* __restrict__ tt) {
    int d = blockIdx.x, b = blockIdx.y;
    int tid = threadIdx.x;
    __shared__ float row[Nn];
    const float* rp = trt + ((size_t)b * Dm + d) * Nn;
    for (int i = tid; i < Nn; i += blockDim.x) row[i] = rp[i];
    __syncthreads();
    float w[5];
#pragma unroll
    for (int j = 0; j < 5; j++) w[j] = tw[d * 5 + j];
    float bb = tb[d];
    float* op = tt + ((size_t)b * Dm + d) * Nn;
    for (int n = tid; n < Nn; n += blockDim.x) {
        float acc = bb;
#pragma unroll
        for (int j = 0; j < 5; j++) {
            int t = n - 2 + j;
            if (t >= 0 && t < Nn) acc += w[j] * row[t];
        }
        op[n] = acc;
    }
}

// ---------------- launch ---------------------------------------------------
extern "C" void kernel_launch(void* const* d_in, const int* in_sizes, int n_in,
                              void* d_out, int out_size) {
    const float* x = (const float*)d_in[0];
    const float* qw = (const float*)d_in[1];  const float* qb = (const float*)d_in[2];
    const float* kw_ = (const float*)d_in[3]; const float* kb = (const float*)d_in[4];
    const float* vw = (const float*)d_in[5];  const float* vb = (const float*)d_in[6];
    const float* ow = (const float*)d_in[7];  const float* ob = (const float*)d_in[8];
    const float* n1g = (const float*)d_in[9]; const float* n1b = (const float*)d_in[10];
    const float* n2g = (const float*)d_in[11]; const float* n2b = (const float*)d_in[12];
    const float* alpha = (const float*)d_in[13];
    const float* dw7 = (const float*)d_in[14];
    const float* dw25 = (const float*)d_in[15];
    const float* dw49 = (const float*)d_in[16];
    const float* router_w = (const float*)d_in[17];
    const float* ew1 = (const float*)d_in[18]; const float* eb1 = (const float*)d_in[19];
    const float* ew2 = (const float*)d_in[20]; const float* eb2 = (const float*)d_in[21];
    const float* tw = (const float*)d_in[22];  const float* tb = (const float*)d_in[23];
    float* out = (float*)d_out;

    float* sc; cudaGetSymbolAddress((void**)&sc, g_scratch);
    int* isc; cudaGetSymbolAddress((void**)&isc, g_iscratch);
    const size_t MM = (size_t)8 * 1024 * 1024;
    const size_t M1 = (size_t)1024 * 1024;
    float* xt = sc;            float* trt = sc + MM;
    float* S  = sc + 2 * MM;   float* Sn  = sc + 3 * MM;
    float* q  = sc + 4 * MM;   float* kk  = sc + 5 * MM;
    float* vv = sc + 6 * MM;   float* y   = sc + 7 * MM;
    float* xs = sc + 8 * MM;   float* xf  = sc + 9 * MM;
    float* hbuf = sc + 10 * MM;
    float* tt = sc + 12 * MM;
    float* gwbuf = sc + 13 * MM;
    float* gatesum = sc + 13 * MM + 4 * Tt_;
    float* qw_r = sc + 14 * MM;
    float* kw_r = qw_r + M1;
    float* vw_r = qw_r + 2 * M1;
    float* ow_r = qw_r + 3 * M1;
    float* ew1_r = qw_r + 4 * M1;   // 8M
    float* ew2_r = qw_r + 12 * M1;  // 8M
    int* icnt = isc;
    int* idxbuf = isc + 64;

    static int smem_set = 0;
    if (!smem_set) {
        cudaFuncSetAttribute(k_sgemm, cudaFuncAttributeMaxDynamicSharedMemorySize, SG_BYTES);
        smem_set = 1;
    }

    dim3 tb32(32, 8);
    k_zero<<<1, 32>>>(icnt, gatesum);
    // round weights to tf32 (rna) once per call
    k_cvt<<<(int)(M1 / 4 + 255) / 256, 256>>>((const float4*)qw, (float4*)qw_r, (int)(M1 / 4));
    k_cvt<<<(int)(M1 / 4 + 255) / 256, 256>>>((const float4*)kw_, (float4*)kw_r, (int)(M1 / 4));
    k_cvt<<<(int)(M1 / 4 + 255) / 256, 256>>>((const float4*)vw, (float4*)vw_r, (int)(M1 / 4));
    k_cvt<<<(int)(M1 / 4 + 255) / 256, 256>>>((const float4*)ow, (float4*)ow_r, (int)(M1 / 4));
    k_cvt<<<(int)(8 * M1 / 4 + 255) / 256, 256>>>((const float4*)ew1, (float4*)ew1_r, (int)(8 * M1 / 4));
    k_cvt<<<(int)(8 * M1 / 4 + 255) / 256, 256>>>((const float4*)ew2, (float4*)ew2_r, (int)(8 * M1 / 4));

    k_transpose<<<dim3(32, 32, Bc), tb32>>>(x, xt);
    k_decomp<<<dim3(Dm, Bc), 128>>>(xt, dw7, dw25, dw49, alpha, trt);
    k_makeS<<<dim3(32, 32, Bc), tb32>>>(x, trt, S);
    k_ln<<<Tt_, 256>>>(S, n1g, n1b, Sn, 1);
    dim3 gqkv(Dm / 128, Tt_ / 128);
    k_sgemm<<<gqkv, 256, SG_BYTES>>>(Sn, qw_r, qb, nullptr, q, Tt_, nullptr, Dm, Dm, nullptr, nullptr, 2);
    k_sgemm<<<gqkv, 256, SG_BYTES>>>(Sn, kw_r, kb, nullptr, kk, Tt_, nullptr, Dm, Dm, nullptr, nullptr, 2);
    k_sgemm<<<gqkv, 256, SG_BYTES>>>(Sn, vw_r, vb, nullptr, vv, Tt_, nullptr, Dm, Dm, nullptr, nullptr, 2);
    k_attn<<<dim3(Nn / 64, Hh, Bc), 128>>>(q, kk, vv, y);
    k_sgemm<<<gqkv, 256, SG_BYTES>>>(y, ow_r, ob, S, xs, Tt_, nullptr, Dm, Dm, nullptr, nullptr, 0);
    k_ln<<<Tt_, 256>>>(xs, n2g, n2b, xf, 1);
    k_router<<<Tt_, 128>>>(xf, router_w, gatesum, icnt, idxbuf, gwbuf);
    k_aux<<<1, 1>>>(gatesum, icnt, out, out_size);
    for (int e = 0; e < NE; e++) {
        k_sgemm<<<dim3(MH / 128, Tt_ / 128), 256, SG_BYTES>>>(
            xf, ew1_r + (size_t)e * MH * Dm, eb1 + e * MH, nullptr, hbuf,
            0, &icnt[e], MH, Dm, idxbuf + e * Tt_, nullptr, 3);
        k_sgemm<<<dim3(Dm / 128, Tt_ / 128), 256, SG_BYTES>>>(
            hbuf, ew2_r + (size_t)e * Dm * MH, eb2 + e * Dm, nullptr, xs,
            0, &icnt[e], Dm, MH, idxbuf + e * Tt_, gwbuf + e * Tt_, 0);
    }
    k_trend<<<dim3(Dm, Bc), 128>>>(trt, tw, tb, tt);
    k_final<<<dim3(32, 32, Bc), tb32>>>(xs, tt, out);
}